// round 17
// baseline (speedup 1.0000x reference)
#include <cuda_runtime.h>
#include <math.h>

// Problem constants (fixed shapes from the reference)
#define B 128
#define C 512
#define HW 1024            // 32*32
#define E 16
#define KTOP 2
#define NOISE_STD_INV 16.0f   // 1 / (1/E) = E
#define TAU 1.0f
#define EPS 1e-8f

// Scratch (no allocations allowed in kernel_launch)
__device__ float g_pooled[B * C];   // 256 KB
__device__ float g_pc[B * E];       // clean softmax probs per row
__device__ float g_pp[B * E];       // load-balance p per row
__device__ int   g_done;            // ticket (self-resetting)

// ---------------------------------------------------------------------------
// Kernel 1: adaptive avg pool.  EXACT proven kernel (83.9% DRAM / 41.0us)
// + PDL trigger.
// ---------------------------------------------------------------------------
__global__ void __launch_bounds__(256) pool_kernel(const float* __restrict__ x) {
    int gwarp = (blockIdx.x * blockDim.x + threadIdx.x) >> 5;
    int lane  = threadIdx.x & 31;

    const float4* row = reinterpret_cast<const float4*>(x + (size_t)gwarp * HW);
    float4 v[8];
#pragma unroll
    for (int j = 0; j < 8; ++j) v[j] = __ldg(&row[lane + 32 * j]);

    float s = 0.0f;
#pragma unroll
    for (int j = 0; j < 8; ++j) s += (v[j].x + v[j].y) + (v[j].z + v[j].w);

#pragma unroll
    for (int o = 16; o; o >>= 1) s += __shfl_xor_sync(0xffffffffu, s, o);
    if (lane == 0) g_pooled[gwarp] = s * (1.0f / (float)HW);

    cudaTriggerProgrammaticLaunchCompletion();
}

// ---------------------------------------------------------------------------
// Kernel 2: block b = GEMM row b + per-row finalize (lanes 0-15, 16-lane
// butterflies, R14-validated); last-arriving block (ticket) does the tiny
// cross-row loss reduction.  All reductions fixed-order -> deterministic.
// ---------------------------------------------------------------------------
__global__ void __launch_bounds__(512) tail_kernel(
        const float* __restrict__ Wg,
        const float* __restrict__ complexity,
        const float* __restrict__ noise,
        float* __restrict__ out) {
    __shared__ float sp[C];
    __shared__ float sLog[E];
    __shared__ int   s_flag;
    __shared__ float part_imp[16][E];
    __shared__ float part_pm[16][E];
    __shared__ float sh_imp[E];
    __shared__ float sh_pm[E];

    const int tid  = threadIdx.x;
    const int we   = tid >> 5;     // warp id == expert for GEMM
    const int lane = tid & 31;
    const int b    = blockIdx.x;

    // ---- PDL prelude (overlaps pool): independent inputs -> registers.
    float wv[C / 32];
    {
        const float* wrow = Wg + we * C;
#pragma unroll
        for (int j = 0; j < C / 32; ++j) wv[j] = __ldg(&wrow[lane + 32 * j]);
    }
    float nz_pre = 0.0f, comp_e = 0.0f;
    if (tid < E) {
        nz_pre = __ldg(&noise[b * E + tid]);
        comp_e = __ldg(&complexity[tid]);
    }

    cudaGridDependencySynchronize();   // pool results visible

    // ---- GEMM: pooled row b staged in smem, warp we -> expert we.
    sp[tid] = g_pooled[b * C + tid];
    __syncthreads();
    {
        float s = 0.0f;
#pragma unroll
        for (int j = 0; j < C / 32; ++j)
            s = fmaf(sp[lane + 32 * j], wv[j], s);
#pragma unroll
        for (int o = 16; o; o >>= 1) s += __shfl_xor_sync(0xffffffffu, s, o);
        if (lane == 0) sLog[we] = s;
    }
    __syncthreads();

    // ---- Per-row finalize on lanes 0-15 of warp 0 (16-lane butterflies).
    if (tid < E) {
        const unsigned M16 = 0x0000ffffu;
        const int e = tid;
        float l  = sLog[e];
        float nz = l + nz_pre;

        // clean softmax prob
        float mx = l;
#pragma unroll
        for (int o = 8; o; o >>= 1) mx = fmaxf(mx, __shfl_xor_sync(M16, mx, o));
        float ex = __expf(l - mx);
        float es = ex;
#pragma unroll
        for (int o = 8; o; o >>= 1) es += __shfl_xor_sync(M16, es, o);
        g_pc[b * E + e] = ex / es;

        // noisy softmax prob
        float mn = nz;
#pragma unroll
        for (int o = 8; o; o >>= 1) mn = fmaxf(mn, __shfl_xor_sync(M16, mn, o));
        float eg = __expf(nz - mn);
        float gs = eg;
#pragma unroll
        for (int o = 8; o; o >>= 1) gs += __shfl_xor_sync(M16, gs, o);
        float g = eg / gs;

        // top-1 of nz (ties -> lowest index, matching jax.lax.top_k)
        float v = nz; int idx = e;
#pragma unroll
        for (int o = 8; o; o >>= 1) {
            float vo = __shfl_xor_sync(M16, v, o);
            int   io = __shfl_xor_sync(M16, idx, o);
            if (vo > v || (vo == v && io < idx)) { v = vo; idx = io; }
        }
        const int i1 = idx;

        // top-2: mask out i1, reduce again
        float vm = (e == i1) ? -3.4e38f : nz;
        int  idx2 = e;
#pragma unroll
        for (int o = 8; o; o >>= 1) {
            float vo = __shfl_xor_sync(M16, vm, o);
            int   io = __shfl_xor_sync(M16, idx2, o);
            if (vo > vm || (vo == vm && io < idx2)) { vm = vo; idx2 = io; }
        }
        const int i2 = idx2;

        float v1  = __shfl_sync(M16, g,  i1);
        float v2  = __shfl_sync(M16, g,  i2);
        float thr = __shfl_sync(M16, nz, i2);

        // outputs for this row
        out[b * E + e] = (e == i1) ? v1 : ((e == i2) ? v2 : 0.0f);
        if (e == 0) {
            out[B * E + b * KTOP + 0]            = (float)i1;
            out[B * E + b * KTOP + 1]            = (float)i2;
            out[B * E + B * KTOP + b * KTOP + 0] = v1;
            out[B * E + B * KTOP + b * KTOP + 1] = v2;
        }

        // load-balance p: 1 - Phi((thr - l)/sigma) = 0.5*erfc(z/sqrt2)
        float z = (thr - l) * NOISE_STD_INV;
        g_pp[b * E + e] = 0.5f * erfcf(z * 0.70710678118654752f);
    }

    // ---- Ticket: last block computes the aux loss.
    __threadfence();
    __syncthreads();
    if (tid == 0) s_flag = (atomicAdd(&g_done, 1) == B - 1);
    __syncthreads();
    if (!s_flag) return;
    __threadfence();   // acquire: all rows' g_pc / g_pp

    // column sums over B: stage 1 = 16 chunks of 8 rows (256 threads)
    if (tid < 256) {
        int ee = tid & 15, chunk = tid >> 4;
        float si = 0.0f, sp2 = 0.0f;
#pragma unroll
        for (int r = chunk * 8; r < chunk * 8 + 8; ++r) {
            si  += g_pc[r * E + ee];
            sp2 += g_pp[r * E + ee];
        }
        part_imp[chunk][ee] = si;
        part_pm[chunk][ee]  = sp2;
    }
    __syncthreads();
    // stage 2: fixed-order combine of 16 partials
    if (tid < E) {
        float si = 0.0f, sp2 = 0.0f;
#pragma unroll
        for (int c = 0; c < 16; ++c) { si += part_imp[c][tid]; sp2 += part_pm[c][tid]; }
        sh_imp[tid] = si * (comp_e * TAU);
        sh_pm[tid]  = sp2 * (1.0f / (float)B);
    }
    __syncthreads();

    if (tid == 0) {
        float mi = 0.0f, mp = 0.0f;
#pragma unroll
        for (int e2 = 0; e2 < E; ++e2) { mi += sh_imp[e2]; mp += sh_pm[e2]; }
        mi *= (1.0f / (float)E);
        mp *= (1.0f / (float)E);
        float vi = 0.0f, vp = 0.0f;
#pragma unroll
        for (int e2 = 0; e2 < E; ++e2) {
            float di = sh_imp[e2] - mi; vi += di * di;
            float dp = sh_pm[e2]  - mp; vp += dp * dp;
        }
        vi *= (1.0f / (float)(E - 1));   // ddof=1
        vp *= (1.0f / (float)(E - 1));
        float cvi = sqrtf(vi) / (mi + EPS);
        float cvp = sqrtf(vp) / (mp + EPS);
        out[B * E + 2 * B * KTOP] = 0.5f * (cvi * cvi) + 0.5f * (cvp * cvp);

        g_done = 0;   // reset ticket for next graph replay
    }
}

// ---------------------------------------------------------------------------
extern "C" void kernel_launch(void* const* d_in, const int* in_sizes, int n_in,
                              void* d_out, int out_size) {
    const float* x          = (const float*)d_in[0];
    const float* W_gate     = (const float*)d_in[1];
    const float* complexity = (const float*)d_in[2];
    const float* noise      = (const float*)d_in[3];
    float* out = (float*)d_out;

    pool_kernel<<<B * C / 8, 256>>>(x);    // proven 83.9% DRAM shape

    // Single PDL tail kernel: GEMM + per-row finalize + ticketed loss.
    cudaLaunchAttribute attr[1];
    attr[0].id = cudaLaunchAttributeProgrammaticStreamSerialization;
    attr[0].val.programmaticStreamSerializationAllowed = 1;

    cudaLaunchConfig_t cfg = {};
    cfg.attrs    = attr;
    cfg.numAttrs = 1;
    cfg.stream   = 0;
    cfg.gridDim  = dim3(B);
    cfg.blockDim = dim3(512);
    cudaLaunchKernelEx(&cfg, tail_kernel, W_gate, complexity, noise, out);
}